// round 9
// baseline (speedup 1.0000x reference)
#include <cuda_runtime.h>
#include <cstdint>

// Plain-LDG streaming reduction (best wallclock architecture) with
// SASS-pinned load batching: asm volatile loads cannot be reordered, so each
// loop iteration issues 8 back-to-back LDGs (6x v4 + 2x scalar) before any
// FMA -> per-warp MLP ~8 instead of the compiler's rolling ~3.
// Fused "last block finishes" finalize, deterministic.

static constexpr int BLOCKS  = 148 * 8;   // 1184 CTAs, 64 warps/SM
static constexpr int THREADS = 256;

__device__ float        g_partials[BLOCKS];
__device__ unsigned int g_done_count;      // zero-init; reset each call

__device__ __forceinline__ float4 ldg_nc_v4(const float4* p) {
    float4 v;
    asm volatile("ld.global.nc.v4.f32 {%0,%1,%2,%3}, [%4];"
                 : "=f"(v.x), "=f"(v.y), "=f"(v.z), "=f"(v.w) : "l"(p));
    return v;
}
__device__ __forceinline__ float4 ldg_cs_v4(const float4* p) {
    float4 v;
    asm volatile("ld.global.cs.nc.v4.f32 {%0,%1,%2,%3}, [%4];"
                 : "=f"(v.x), "=f"(v.y), "=f"(v.z), "=f"(v.w) : "l"(p));
    return v;
}
__device__ __forceinline__ float ldg_nc_f(const float* p) {
    float v;
    asm volatile("ld.global.nc.f32 %0, [%1];" : "=f"(v) : "l"(p));
    return v;
}

__global__ __launch_bounds__(THREADS) void trajloss_batched_kernel(
    const float* __restrict__ pred,   // N+1
    const float* __restrict__ xs,     // N
    const float* __restrict__ ys,     // N
    float* __restrict__ out,
    int n4)                           // N/4
{
    const float4* __restrict__ pred4 = reinterpret_cast<const float4*>(pred);
    const float4* __restrict__ x4    = reinterpret_cast<const float4*>(xs);
    const float4* __restrict__ y4    = reinterpret_cast<const float4*>(ys);

    float acc0 = 0.0f, acc1 = 0.0f;

    const int stride = BLOCKS * THREADS;
    int i = blockIdx.x * THREADS + threadIdx.x;

    // ---- main loop: 2 grid-stride steps, 8 loads pinned back-to-back ----
    for (; i + stride < n4; i += 2 * stride) {
        int j = i + stride;
        // SASS-ordered load burst (asm volatile preserves program order):
        float4 p0  = ldg_nc_v4(&pred4[i]);
        float4 xv0 = ldg_cs_v4(&x4[i]);
        float4 yv0 = ldg_cs_v4(&y4[i]);
        float4 p1  = ldg_nc_v4(&pred4[j]);
        float4 xv1 = ldg_cs_v4(&x4[j]);
        float4 yv1 = ldg_cs_v4(&y4[j]);
        float  s0  = ldg_nc_f(&pred[i * 4 + 4]);
        float  s1  = ldg_nc_f(&pred[j * 4 + 4]);

        {
            float dx0 = xv0.x - p0.x, dx1 = xv0.y - p0.y;
            float dx2 = xv0.z - p0.z, dx3 = xv0.w - p0.w;
            float dy0 = yv0.x - p0.y, dy1 = yv0.y - p0.z;
            float dy2 = yv0.z - p0.w, dy3 = yv0.w - s0;
            acc0 = fmaf(dx0, dx0, acc0); acc1 = fmaf(dy0, dy0, acc1);
            acc0 = fmaf(dx1, dx1, acc0); acc1 = fmaf(dy1, dy1, acc1);
            acc0 = fmaf(dx2, dx2, acc0); acc1 = fmaf(dy2, dy2, acc1);
            acc0 = fmaf(dx3, dx3, acc0); acc1 = fmaf(dy3, dy3, acc1);
        }
        {
            float dx0 = xv1.x - p1.x, dx1 = xv1.y - p1.y;
            float dx2 = xv1.z - p1.z, dx3 = xv1.w - p1.w;
            float dy0 = yv1.x - p1.y, dy1 = yv1.y - p1.z;
            float dy2 = yv1.z - p1.w, dy3 = yv1.w - s1;
            acc0 = fmaf(dx0, dx0, acc0); acc1 = fmaf(dy0, dy0, acc1);
            acc0 = fmaf(dx1, dx1, acc0); acc1 = fmaf(dy1, dy1, acc1);
            acc0 = fmaf(dx2, dx2, acc0); acc1 = fmaf(dy2, dy2, acc1);
            acc0 = fmaf(dx3, dx3, acc0); acc1 = fmaf(dy3, dy3, acc1);
        }
    }

    // ---- remainder: at most one step ----
    for (; i < n4; i += stride) {
        float4 p  = ldg_nc_v4(&pred4[i]);
        float4 xv = ldg_cs_v4(&x4[i]);
        float4 yv = ldg_cs_v4(&y4[i]);
        float  s  = ldg_nc_f(&pred[i * 4 + 4]);

        float dx0 = xv.x - p.x, dx1 = xv.y - p.y;
        float dx2 = xv.z - p.z, dx3 = xv.w - p.w;
        float dy0 = yv.x - p.y, dy1 = yv.y - p.z;
        float dy2 = yv.z - p.w, dy3 = yv.w - s;
        acc0 = fmaf(dx0, dx0, acc0); acc1 = fmaf(dy0, dy0, acc1);
        acc0 = fmaf(dx1, dx1, acc0); acc1 = fmaf(dy1, dy1, acc1);
        acc0 = fmaf(dx2, dx2, acc0); acc1 = fmaf(dy2, dy2, acc1);
        acc0 = fmaf(dx3, dx3, acc0); acc1 = fmaf(dy3, dy3, acc1);
    }

    float acc = acc0 + acc1;

    // ---- intra-block reduction ----
    #pragma unroll
    for (int off = 16; off > 0; off >>= 1)
        acc += __shfl_xor_sync(0xFFFFFFFFu, acc, off);

    __shared__ float warp_sums[THREADS / 32];
    __shared__ bool  is_last;
    int lane = threadIdx.x & 31;
    int wid  = threadIdx.x >> 5;
    if (lane == 0) warp_sums[wid] = acc;
    __syncthreads();

    if (wid == 0) {
        float v = (lane < THREADS / 32) ? warp_sums[lane] : 0.0f;
        #pragma unroll
        for (int off = 4; off > 0; off >>= 1)
            v += __shfl_xor_sync(0xFFFFFFFFu, v, off);
        if (lane == 0) {
            g_partials[blockIdx.x] = v;
            __threadfence();
            unsigned int prev = atomicAdd(&g_done_count, 1u);
            is_last = (prev == (unsigned int)(BLOCKS - 1));
        }
    }
    __syncthreads();

    // ---- last block reduces all partials ----
    if (is_last) {
        float t = 0.0f;
        for (int k = threadIdx.x; k < BLOCKS; k += THREADS)
            t += g_partials[k];

        #pragma unroll
        for (int off = 16; off > 0; off >>= 1)
            t += __shfl_xor_sync(0xFFFFFFFFu, t, off);

        if (lane == 0) warp_sums[wid] = t;
        __syncthreads();

        if (wid == 0) {
            float v = (lane < THREADS / 32) ? warp_sums[lane] : 0.0f;
            #pragma unroll
            for (int off = 4; off > 0; off >>= 1)
                v += __shfl_xor_sync(0xFFFFFFFFu, v, off);
            if (lane == 0) {
                out[0] = v;
                g_done_count = 0;     // graph-replay safe reset
            }
        }
    }
}

extern "C" void kernel_launch(void* const* d_in, const int* in_sizes, int n_in,
                              void* d_out, int out_size)
{
    const float* pred = (const float*)d_in[0];   // N+1
    const float* xs   = (const float*)d_in[1];   // N
    const float* ys   = (const float*)d_in[2];   // N
    float* out        = (float*)d_out;

    int n  = in_sizes[1];
    int n4 = n >> 2;

    trajloss_batched_kernel<<<BLOCKS, THREADS>>>(pred, xs, ys, out, n4);
}

// round 10
// speedup vs baseline: 1.1393x; 1.1393x over previous
#include <cuda_runtime.h>

// Plain-LDG streaming reduction (wallclock-best architecture, R2) with the
// redundant shifted-scalar LDG replaced by a warp shuffle:
//   pred[4i+4] == (lane+1)'s p.x  -> __shfl_down_sync, free via RF.
//   Only lane 31 loads the cross-warp boundary scalar (1 line/warp vs 4).
// Cuts 25% of L1tex wavefront traffic. Fused last-block finalize.

static constexpr int BLOCKS  = 148 * 8;   // 1184 CTAs, 64 warps/SM
static constexpr int THREADS = 256;

__device__ float        g_partials[BLOCKS];
__device__ unsigned int g_done_count;      // zero-init; reset each call

__global__ __launch_bounds__(THREADS) void trajloss_shfl_kernel(
    const float* __restrict__ pred,   // N+1 elements
    const float* __restrict__ xs,     // N elements
    const float* __restrict__ ys,     // N elements
    float* __restrict__ out,
    int n4)                           // N / 4
{
    const float4* __restrict__ pred4 = reinterpret_cast<const float4*>(pred);
    const float4* __restrict__ x4    = reinterpret_cast<const float4*>(xs);
    const float4* __restrict__ y4    = reinterpret_cast<const float4*>(ys);

    float acc0 = 0.0f, acc1 = 0.0f;

    const int stride = BLOCKS * THREADS;
    const int lane   = threadIdx.x & 31;
    int idx = blockIdx.x * THREADS + threadIdx.x;

    // Main loop bound such that the i < bound guard is warp-uniform:
    // stride % 32 == 0 and warp-base of idx % 32 == 0, so any multiple-of-32
    // bound keeps whole warps together. (n4 = 4M is already a multiple of 32.)
    const int bound = n4 & ~31;

    #pragma unroll 4
    for (int i = idx; i < bound; i += stride) {
        float4 p  = pred4[i];
        float4 xv = __ldcs(&x4[i]);
        float4 yv = __ldcs(&y4[i]);

        // pred[4i+4]: neighbor lane's p.x; lane 31 loads across warp boundary.
        float pn = __shfl_down_sync(0xFFFFFFFFu, p.x, 1);
        if (lane == 31) pn = __ldg(&pred[i * 4 + 4]);

        float dx0 = xv.x - p.x, dx1 = xv.y - p.y;
        float dx2 = xv.z - p.z, dx3 = xv.w - p.w;
        float dy0 = yv.x - p.y, dy1 = yv.y - p.z;
        float dy2 = yv.z - p.w, dy3 = yv.w - pn;

        acc0 = fmaf(dx0, dx0, acc0); acc1 = fmaf(dy0, dy0, acc1);
        acc0 = fmaf(dx1, dx1, acc0); acc1 = fmaf(dy1, dy1, acc1);
        acc0 = fmaf(dx2, dx2, acc0); acc1 = fmaf(dy2, dy2, acc1);
        acc0 = fmaf(dx3, dx3, acc0); acc1 = fmaf(dy3, dy3, acc1);
    }

    // Shuffle-free remainder (handles n4 not multiple of 32; zero iters here).
    for (int i = (idx >= bound ? idx : idx + ((bound - idx + stride - 1) / stride) * stride);
         i < n4; i += stride) {
        float4 p  = pred4[i];
        float4 xv = __ldcs(&x4[i]);
        float4 yv = __ldcs(&y4[i]);
        float  pn = __ldg(&pred[i * 4 + 4]);

        float dx0 = xv.x - p.x, dx1 = xv.y - p.y;
        float dx2 = xv.z - p.z, dx3 = xv.w - p.w;
        float dy0 = yv.x - p.y, dy1 = yv.y - p.z;
        float dy2 = yv.z - p.w, dy3 = yv.w - pn;

        acc0 = fmaf(dx0, dx0, acc0); acc1 = fmaf(dy0, dy0, acc1);
        acc0 = fmaf(dx1, dx1, acc0); acc1 = fmaf(dy1, dy1, acc1);
        acc0 = fmaf(dx2, dx2, acc0); acc1 = fmaf(dy2, dy2, acc1);
        acc0 = fmaf(dx3, dx3, acc0); acc1 = fmaf(dy3, dy3, acc1);
    }

    float acc = acc0 + acc1;

    // ---- intra-block reduction ----
    #pragma unroll
    for (int off = 16; off > 0; off >>= 1)
        acc += __shfl_xor_sync(0xFFFFFFFFu, acc, off);

    __shared__ float warp_sums[THREADS / 32];
    __shared__ bool  is_last;
    int wid = threadIdx.x >> 5;
    if (lane == 0) warp_sums[wid] = acc;
    __syncthreads();

    if (wid == 0) {
        float v = (lane < THREADS / 32) ? warp_sums[lane] : 0.0f;
        #pragma unroll
        for (int off = 4; off > 0; off >>= 1)
            v += __shfl_xor_sync(0xFFFFFFFFu, v, off);
        if (lane == 0) {
            g_partials[blockIdx.x] = v;
            __threadfence();
            unsigned int prev = atomicAdd(&g_done_count, 1u);
            is_last = (prev == (unsigned int)(BLOCKS - 1));
        }
    }
    __syncthreads();

    // ---- last block reduces all partials ----
    if (is_last) {
        float t = 0.0f;
        for (int k = threadIdx.x; k < BLOCKS; k += THREADS)
            t += g_partials[k];

        #pragma unroll
        for (int off = 16; off > 0; off >>= 1)
            t += __shfl_xor_sync(0xFFFFFFFFu, t, off);

        if (lane == 0) warp_sums[wid] = t;
        __syncthreads();

        if (wid == 0) {
            float v = (lane < THREADS / 32) ? warp_sums[lane] : 0.0f;
            #pragma unroll
            for (int off = 4; off > 0; off >>= 1)
                v += __shfl_xor_sync(0xFFFFFFFFu, v, off);
            if (lane == 0) {
                out[0] = v;
                g_done_count = 0;     // graph-replay safe reset
            }
        }
    }
}

extern "C" void kernel_launch(void* const* d_in, const int* in_sizes, int n_in,
                              void* d_out, int out_size)
{
    const float* pred = (const float*)d_in[0];   // N+1
    const float* xs   = (const float*)d_in[1];   // N
    const float* ys   = (const float*)d_in[2];   // N
    float* out        = (float*)d_out;

    int n  = in_sizes[1];
    int n4 = n >> 2;

    trajloss_shfl_kernel<<<BLOCKS, THREADS>>>(pred, xs, ys, out, n4);
}